// round 2
// baseline (speedup 1.0000x reference)
#include <cuda_runtime.h>

// Inputs (metadata order):
//   d_in[0] sample       int32  [B,3]      (head, rel, tail)
//   d_in[1] entity_emb   f32    [E,128]
//   d_in[2] relation_emb f32    [R,128]    (unused by the math)
//   d_in[3] type_emb     f32    [T*R, 128*128]
//   d_in[4] node_type    int32  [E]
// Output: f32 [B] scores.
//
// Algebra: score uses only he[0..2]; elementwise normalization means we only
// need rows 0..2 of each 128x128 matrix -> 3 dot products per sample.
//
// Layout: one sample per 8-lane group (4 samples/warp). Each lane owns 16
// floats (4x float4) of h and of each matrix row -> 16 independent ld.128 per
// lane, 4 independent index chains per warp. Reduction = 3 shfl steps inside
// the 8-lane group.

#define D    128
#define TLEN 16   // T = type_emb rows / R = 3200/200
#define SPW  4    // samples per warp (8 lanes each)

__global__ __launch_bounds__(128) void ttd_transe_kernel(
    const int*   __restrict__ sample,
    const float* __restrict__ entity_emb,
    const float* __restrict__ type_emb,
    const int*   __restrict__ node_type,
    float*       __restrict__ out,
    int B)
{
    const int warp = (blockIdx.x * blockDim.x + threadIdx.x) >> 5;
    const int lane = threadIdx.x & 31;
    const int g    = lane >> 3;      // group 0..3 within warp
    const int gl   = lane & 7;       // lane 0..7 within group
    const int s    = warp * SPW + g; // sample index
    if (s >= B) return;

    // Index chain (one distinct address per 8-lane group; broadcast within).
    const int head = __ldg(&sample[s * 3 + 0]);
    const int rel  = __ldg(&sample[s * 3 + 1]);
    const int mrow = rel * TLEN + __ldg(&node_type[head]);

    const float4* __restrict__ h4 =
        reinterpret_cast<const float4*>(entity_emb + (long long)head * D);
    const float4* __restrict__ m4 =
        reinterpret_cast<const float4*>(type_emb + (long long)mrow * (long long)(D * D));

    // Lane gl covers float4 slots {gl, gl+8, gl+16, gl+24} of each 128-float
    // vector: each ld.128 is a contiguous 128B segment per group.
    float4 hv[4], r0[4], r1[4], r2[4];
    #pragma unroll
    for (int i = 0; i < 4; i++) {
        const int idx = gl + 8 * i;
        hv[i] = h4[idx];
        r0[i] = m4[idx];          // matrix row 0
        r1[i] = m4[32 + idx];     // matrix row 1
        r2[i] = m4[64 + idx];     // matrix row 2
    }

    float s0 = 0.f, s1 = 0.f, s2 = 0.f;
    #pragma unroll
    for (int i = 0; i < 4; i++) {
        s0 = fmaf(hv[i].x, r0[i].x, fmaf(hv[i].y, r0[i].y,
             fmaf(hv[i].z, r0[i].z, fmaf(hv[i].w, r0[i].w, s0))));
        s1 = fmaf(hv[i].x, r1[i].x, fmaf(hv[i].y, r1[i].y,
             fmaf(hv[i].z, r1[i].z, fmaf(hv[i].w, r1[i].w, s1))));
        s2 = fmaf(hv[i].x, r2[i].x, fmaf(hv[i].y, r2[i].y,
             fmaf(hv[i].z, r2[i].z, fmaf(hv[i].w, r2[i].w, s2))));
    }

    // Butterfly reduce inside the 8-lane group (xor offsets < 8 stay in-group).
    #pragma unroll
    for (int off = 4; off > 0; off >>= 1) {
        s0 += __shfl_xor_sync(0xFFFFFFFFu, s0, off);
        s1 += __shfl_xor_sync(0xFFFFFFFFu, s1, off);
        s2 += __shfl_xor_sync(0xFFFFFFFFu, s2, off);
    }

    if (gl == 0) {
        const float eps = 1e-12f;
        const float a = s0 / fmaxf(fabsf(s0), eps);
        const float b = s1 / fmaxf(fabsf(s1), eps);
        const float c = s2 / fmaxf(fabsf(s2), eps);
        out[s] = fabsf(a + b - c + 1e-6f);  // leaders write 4 consecutive floats
    }
}

extern "C" void kernel_launch(void* const* d_in, const int* in_sizes, int n_in,
                              void* d_out, int out_size)
{
    const int*   sample     = (const int*)  d_in[0];
    const float* entity_emb = (const float*)d_in[1];
    // d_in[2] relation_emb unused
    const float* type_emb   = (const float*)d_in[3];
    const int*   node_type  = (const int*)  d_in[4];
    float* out = (float*)d_out;

    const int B = out_size;                     // 8192
    const int threads = 128;                    // 4 warps/block
    const int samples_per_block = (threads / 32) * SPW;  // 16
    const int blocks = (B + samples_per_block - 1) / samples_per_block;  // 512

    ttd_transe_kernel<<<blocks, threads>>>(sample, entity_emb, type_emb,
                                           node_type, out, B);
}

// round 3
// speedup vs baseline: 1.2047x; 1.2047x over previous
#include <cuda_runtime.h>

// Inputs (metadata order):
//   d_in[0] sample       int32  [B,3]      (head, rel, tail)
//   d_in[1] entity_emb   f32    [E,128]
//   d_in[2] relation_emb f32    [R,128]    (unused by the math)
//   d_in[3] type_emb     f32    [T*R, 128*128]
//   d_in[4] node_type    int32  [E]
// Output: f32 [B] scores.
//
// Algebra: score uses only he[0..2]; elementwise normalization means we only
// need rows 0..2 of each 128x128 matrix -> 3 dot products per sample.
//
// Layout: one warp per sample (R1 structure — single full wave of 8192 warps,
// best chain-latency hiding). Entity gathers use __ldcs (streaming/evict-first)
// so they don't evict the reused type_emb/node_type working set from L2.

#define D    128
#define TLEN 16   // T = type_emb rows / R = 3200/200

__global__ __launch_bounds__(256, 8) void ttd_transe_kernel(
    const int*   __restrict__ sample,
    const float* __restrict__ entity_emb,
    const float* __restrict__ type_emb,
    const int*   __restrict__ node_type,
    float*       __restrict__ out,
    int B)
{
    const int gwarp = (blockIdx.x * blockDim.x + threadIdx.x) >> 5;
    const int lane  = threadIdx.x & 31;
    if (gwarp >= B) return;

    // Dependent index chain (broadcast within warp -> 1 L1 transaction each).
    const int head = __ldg(&sample[gwarp * 3 + 0]);
    const int rel  = __ldg(&sample[gwarp * 3 + 1]);
    const int mrow = rel * TLEN + __ldg(&node_type[head]);

    // All offsets fit comfortably in int32 (max type_emb elem idx = 52.4M).
    const float4* __restrict__ h4 =
        reinterpret_cast<const float4*>(entity_emb) + head * (D / 4);
    const float4* __restrict__ m4 =
        reinterpret_cast<const float4*>(type_emb) + mrow * (D * D / 4);

    // Lane l owns floats [4l, 4l+4) of each 128-float vector (coalesced 512B).
    // Entity row: streaming load (no reuse, don't pollute L2).
    const float4 hv = __ldcs(&h4[lane]);
    // Matrix rows 0..2: default caching (3200-matrix working set, heavy reuse).
    const float4 r0 = __ldg(&m4[lane]);
    const float4 r1 = __ldg(&m4[32 + lane]);
    const float4 r2 = __ldg(&m4[64 + lane]);

    float s0 = hv.x * r0.x + hv.y * r0.y + hv.z * r0.z + hv.w * r0.w;
    float s1 = hv.x * r1.x + hv.y * r1.y + hv.z * r1.z + hv.w * r1.w;
    float s2 = hv.x * r2.x + hv.y * r2.y + hv.z * r2.z + hv.w * r2.w;

    #pragma unroll
    for (int off = 16; off > 0; off >>= 1) {
        s0 += __shfl_xor_sync(0xFFFFFFFFu, s0, off);
        s1 += __shfl_xor_sync(0xFFFFFFFFu, s1, off);
        s2 += __shfl_xor_sync(0xFFFFFFFFu, s2, off);
    }

    if (lane == 0) {
        const float eps = 1e-12f;
        const float a = s0 / fmaxf(fabsf(s0), eps);
        const float b = s1 / fmaxf(fabsf(s1), eps);
        const float c = s2 / fmaxf(fabsf(s2), eps);
        out[gwarp] = fabsf(a + b - c + 1e-6f);
    }
}

extern "C" void kernel_launch(void* const* d_in, const int* in_sizes, int n_in,
                              void* d_out, int out_size)
{
    const int*   sample     = (const int*)  d_in[0];
    const float* entity_emb = (const float*)d_in[1];
    // d_in[2] relation_emb unused
    const float* type_emb   = (const float*)d_in[3];
    const int*   node_type  = (const int*)  d_in[4];
    float* out = (float*)d_out;

    const int B = out_size;                 // 8192
    const int threads = 256;                // 8 warps/block, warp per sample
    const int warps_per_block = threads / 32;
    const int blocks = (B + warps_per_block - 1) / warps_per_block;  // 1024

    ttd_transe_kernel<<<blocks, threads>>>(sample, entity_emb, type_emb,
                                           node_type, out, B);
}